// round 17
// baseline (speedup 1.0000x reference)
#include <cuda_runtime.h>

#define NTRAJ  2048
#define TSTEPS 512
#define KDIM   (TSTEPS * 3)
#define NCH    (3 * NTRAJ)
#define PF     8
#define DT     0.00833333333333333f

// x/y paired partials: g_part4[(t>>1)*(2*NTRAJ) + c*NTRAJ + traj] =
// (S_t, M_t, S_{t+1}, M_{t+1}).  16.8 MB.
__device__ float4 g_part4[(TSTEPS / 2) * 2 * NTRAJ];
// theta Mahalanobis partials (M only): 4.2 MB.
__device__ float2 g_mth[(TSTEPS / 2) * NTRAJ];
// shared theta innovation variance: identical for ALL trajectories (a == 1,
// P-recursion is measurement-independent). 2 KB.
__device__ float  g_sth[TSTEPS];

__device__ __forceinline__ float htanh(float x) {
    float y; asm("tanh.approx.f32 %0, %1;" : "=f"(y) : "f"(x)); return y;
}
__device__ __forceinline__ float frcp(float x) {
    float y; asm("rcp.approx.f32 %0, %1;" : "=f"(y) : "f"(x)); return y;
}

// Deferred-normalization Kalman step (R16-exact arithmetic, rel 1.8e-4):
// covariance tracked as u = P*d, d renormalized to S_true each step; the
// carried P-loop has no reciprocal on it.
struct KState {
    float s0, s1;
    float u00, u01, u11;
    float d, invd, invd2;
    float rd, q0d, q1d, rinvd;
};

__device__ __forceinline__ void kstep_dn(
    KState& k, float z, float c1, float c2, float c3, float c4,
    float q0, float q1, float r, float& S_out, float& M_out)
{
    float sp = fmaf(DT, k.s1, k.s0);
    float tv = htanh(100.0f * k.s1);
    float vp = fmaf(-c2, tv, c1 * k.s1);
    float a  = fmaf(c3, tv * tv, c4);

    float w   = fmaf(DT, k.u11, k.u01);
    float n00 = fmaf(DT, w, fmaf(DT, k.u01, k.u00)) + k.q0d;
    float n01 = a * w;
    float n11 = fmaf(a * a, k.u11, k.q1d);

    float sig  = n00 + k.rd;
    float invs = frcp(sig);
    float S    = __fmul_rn(sig, k.invd);
    float yv   = z - sp;
    float K0   = __fmul_rn(n00, invs);
    float K1   = __fmul_rn(n01, invs);
    k.s0 = fmaf(K0, yv, sp);
    k.s1 = fmaf(K1, yv, vp);

    float dinvs = __fmul_rn(k.d, invs);
    M_out = __fmul_rn(yv * yv, dinvs);
    S_out = S;

    float t1 = fmaf(n11, sig, -(n01 * n01));
    k.u00 = __fmul_rn(k.rinvd, n00);
    k.u01 = __fmul_rn(k.rinvd, n01);
    k.u11 = __fmul_rn(t1, k.invd2);

    k.d    = S;
    k.invd = dinvs;
    k.rd    = r  * S;
    k.q0d   = q0 * S;
    k.q1d   = q1 * S;
    k.rinvd = r * dinvs;
    k.invd2 = dinvs * dinvs;
}

// 6144 chains, one per lane. Warps never straddle components (2048 % 32 == 0),
// so the x/y-vs-theta store paths are warp-uniform.
__global__ void __launch_bounds__(32, 1) ekf_k(
    const float* __restrict__ meas,
    const float* __restrict__ init_state,
    const float* __restrict__ dyna,
    const float* __restrict__ Q,
    const float* __restrict__ R,
    const float* __restrict__ P0)
{
    const int lane  = threadIdx.x & 31;
    const int chain = blockIdx.x * 32 + lane;
    const int c     = chain >> 11;          // 0,1,2
    const int traj  = chain & (NTRAJ - 1);

    const bool lin = (c == 2);
    const float fric = lin ? 0.0f : __ldg(dyna + 0);
    const float damp = lin ? 0.0f : __ldg(dyna + 1);

    const float c1 = 1.0f - DT * damp;
    const float c2 = DT * fric;
    const float c3 = 100.0f * c2;
    const float c4 = c1 - c3;

    const int pc = lin ? 4 : c;
    const int vc = lin ? 5 : c + 2;

    const float q0 = __ldg(Q + pc * 7);
    const float q1 = __ldg(Q + vc * 7);
    const float r  = __ldg(R + c * 4);

    KState k;
    k.s0 = init_state[traj * 6 + pc];
    k.s1 = init_state[traj * 6 + vc];
    k.u00 = __ldg(P0 + pc * 7);
    k.u01 = __ldg(P0 + pc * 6 + vc);
    k.u11 = __ldg(P0 + vc * 7);
    k.d = 1.0f; k.invd = 1.0f; k.invd2 = 1.0f;
    k.rd = r; k.q0d = q0; k.q1d = q1; k.rinvd = r;

    const float* zb = meas + traj * KDIM + c;   // z(t) at zb[3*t]
    float4* pp4 = g_part4 + (c * NTRAJ + traj);        // valid for c<2
    float2* pp2 = g_mth + traj;                        // valid for c==2
    const bool swrite = (chain == 2 * NTRAJ);          // traj 0 of theta

    float zr[PF];
    #pragma unroll
    for (int i = 0; i < PF; ++i) zr[i] = zb[3 * i];

    const float* pz = zb + 3 * PF;

    float Sp, Mp;

    #pragma unroll 1
    for (int t = 0; t < TSTEPS - PF; t += PF) {
        #pragma unroll
        for (int u8 = 0; u8 < PF; ++u8) {
            float z = zr[u8];
            zr[u8] = pz[3 * u8];
            float S, M;
            kstep_dn(k, z, c1, c2, c3, c4, q0, q1, r, S, M);
            if (swrite) g_sth[t + u8] = S;
            if ((u8 & 1) == 0) { Sp = S; Mp = M; }
            else if (c < 2) pp4[(u8 >> 1) * 2 * NTRAJ] = make_float4(Sp, Mp, S, M);
            else            pp2[(u8 >> 1) * NTRAJ]     = make_float2(Mp, M);
        }
        pz  += 3 * PF;
        pp4 += (PF / 2) * 2 * NTRAJ;
        pp2 += (PF / 2) * NTRAJ;
    }
    #pragma unroll
    for (int u8 = 0; u8 < PF; ++u8) {
        float S, M;
        kstep_dn(k, zr[u8], c1, c2, c3, c4, q0, q1, r, S, M);
        if (swrite) g_sth[TSTEPS - PF + u8] = S;
        if ((u8 & 1) == 0) { Sp = S; Mp = M; }
        else if (c < 2) pp4[(u8 >> 1) * 2 * NTRAJ] = make_float4(Sp, Mp, S, M);
        else            pp2[(u8 >> 1) * NTRAJ]     = make_float2(Mp, M);
    }
}

// loss[traj][t] = (Sx*Sy)*Sth + (mx+my)+mth; Sth from the shared array.
__global__ void combine_k(float* __restrict__ out) {
    __shared__ float tile[32][33];        // [t][traj]
    const int t0  = blockIdx.x * 32;
    const int tr0 = blockIdx.y * 32;
    const int tx = threadIdx.x, ty = threadIdx.y;   // ty in 0..15

    const int tp = t0 / 2 + ty;
    const float4* base = g_part4 + tp * 2 * NTRAJ + tr0 + tx;
    float4 px = base[0];
    float4 py = base[NTRAJ];
    float2 mt = g_mth[tp * NTRAJ + tr0 + tx];
    float  s0 = g_sth[t0 + 2 * ty];
    float  s1 = g_sth[t0 + 2 * ty + 1];
    tile[2 * ty][tx]     = fmaf(px.x * py.x, s0, (px.y + py.y) + mt.x);
    tile[2 * ty + 1][tx] = fmaf(px.z * py.z, s1, (px.w + py.w) + mt.y);
    __syncthreads();
    out[(tr0 + ty) * TSTEPS + t0 + tx]      = tile[tx][ty];
    out[(tr0 + ty + 16) * TSTEPS + t0 + tx] = tile[tx][ty + 16];
}

extern "C" void kernel_launch(void* const* d_in, const int* in_sizes, int n_in,
                              void* d_out, int out_size) {
    const float* meas = (const float*)d_in[0];
    const float* init = (const float*)d_in[1];
    const float* dyna = (const float*)d_in[2];
    const float* Q    = (const float*)d_in[3];
    const float* R    = (const float*)d_in[4];
    const float* P0   = (const float*)d_in[5];
    float* out = (float*)d_out;

    ekf_k<<<NCH / 32, 32>>>(meas, init, dyna, Q, R, P0);
    dim3 cgrid(TSTEPS / 32, NTRAJ / 32);
    combine_k<<<cgrid, dim3(32, 16)>>>(out);
}